// round 3
// baseline (speedup 1.0000x reference)
#include <cuda_runtime.h>
#include <cuda_fp16.h>
#include <cstdint>

#define N_NODES 10000
#define N_EDGES 640000
#define D 128

#define GEMM_BLOCKS 1250   // 8 nodes per block
#define HIST_BLOCKS 625    // 1024 edges per block (exact: 625*1024 = 640000)

// ---- allocation-free scratch ----------------------------------------------
__device__ __half g_yh[N_NODES * D];   // y = x @ W^T, fp16 (2.5MB, L2-resident)
__device__ int    g_count[N_NODES];    // zero-init; scan re-zeroes each run
__device__ int    g_cursor[N_NODES];   // excl prefix -> (after fill) incl prefix
__device__ int    g_esrc[N_EDGES];
__device__ float  g_eval[N_EDGES];

// Per-block index-dtype sniff: warp 0 tests 32 int64-interpretations.
// For int32 data, P(all valid node ids) ~ (1e-4)^32 -> effectively 0.
__device__ __forceinline__ int block_sniff_idx64(const void* idxp, int t,
                                                 int* s_flag) {
    if (t < 32) {
        long long v = ((const long long*)idxp)[t];
        int ok = (v >= 0 && v < N_NODES);
        int all = __all_sync(0xFFFFFFFFu, ok);
        if (t == 0) *s_flag = all;
    }
    __syncthreads();
    return *s_flag;
}

// ---------------------------------------------------------------------------
// Fused kernel: blocks [0, GEMM_BLOCKS) compute y = x@W^T (fp16 out);
// blocks [GEMM_BLOCKS, +HIST_BLOCKS) histogram dst into g_count.
// 256 threads per block for both roles.
// ---------------------------------------------------------------------------
__global__ void __launch_bounds__(256) gemm_hist_kernel(
    const float* __restrict__ x, const float* __restrict__ W,
    const void* __restrict__ dstp)
{
    int t = threadIdx.x;

    if (blockIdx.x < GEMM_BLOCKS) {
        // ---- GEMM part: 8 nodes/block, 2 groups of 128 threads x 4 nodes --
        __shared__ float4 xs[8][32];
        int n0 = blockIdx.x * 8;
        int o  = t & 127;         // output column
        int g  = t >> 7;          // group 0/1 -> nodes [g*4, g*4+4)

        // stage 8 rows = 256 float4 loads, one per thread
        {
            int n = t >> 5, c = t & 31;
            int node = n0 + n;
            xs[n][c] = (node < N_NODES) ? ((const float4*)x)[node * 32 + c]
                                        : make_float4(0.f, 0.f, 0.f, 0.f);
        }
        __syncthreads();

        float acc[4] = {0.f, 0.f, 0.f, 0.f};
        const float4* Wo = (const float4*)(W + o * D);
#pragma unroll 8
        for (int c = 0; c < 32; c++) {
            float4 w = __ldg(&Wo[c]);
#pragma unroll
            for (int n = 0; n < 4; n++) {
                float4 xv = xs[g * 4 + n][c];
                acc[n] += w.x * xv.x + w.y * xv.y + w.z * xv.z + w.w * xv.w;
            }
        }
#pragma unroll
        for (int n = 0; n < 4; n++) {
            int node = n0 + g * 4 + n;
            if (node < N_NODES) g_yh[node * D + o] = __float2half(acc[n]);
        }
    } else {
        // ---- HIST part: 4 edges/thread, vectorized loads ------------------
        __shared__ int s_flag;
        int idx64 = block_sniff_idx64(dstp, t, &s_flag);

        int hb = blockIdx.x - GEMM_BLOCKS;
        int e0 = (hb * 256 + t) * 4;

        int d0, d1, d2, d3;
        if (idx64) {
            const longlong2* p = (const longlong2*)dstp;
            longlong2 a = __ldg(&p[e0 >> 1]);
            longlong2 c = __ldg(&p[(e0 >> 1) + 1]);
            d0 = (int)a.x; d1 = (int)a.y; d2 = (int)c.x; d3 = (int)c.y;
        } else {
            int4 a = __ldg(&((const int4*)dstp)[e0 >> 2]);
            d0 = a.x; d1 = a.y; d2 = a.z; d3 = a.w;
        }
        asm volatile("red.global.add.s32 [%0], %1;" :: "l"(g_count + d0), "r"(1) : "memory");
        asm volatile("red.global.add.s32 [%0], %1;" :: "l"(g_count + d1), "r"(1) : "memory");
        asm volatile("red.global.add.s32 [%0], %1;" :: "l"(g_count + d2), "r"(1) : "memory");
        asm volatile("red.global.add.s32 [%0], %1;" :: "l"(g_count + d3), "r"(1) : "memory");
    }
}

// ---------------------------------------------------------------------------
// Shuffle-based exclusive scan: 1024 threads x 10 nodes each.
// Writes g_cursor (exclusive prefix) and re-zeroes g_count for next replay.
// ---------------------------------------------------------------------------
__global__ void __launch_bounds__(1024) scan_kernel() {
    __shared__ int warp_sums[32];
    const int PER = 10;                 // 1024*10 = 10240 >= 10000
    int t = threadIdx.x;
    int lane = t & 31, w = t >> 5;
    int base = t * PER;

    int c[PER];
    int s = 0;
#pragma unroll
    for (int i = 0; i < PER; i++) {
        c[i] = (base + i < N_NODES) ? g_count[base + i] : 0;
        s += c[i];
    }

    // warp inclusive scan of s
    int incl = s;
#pragma unroll
    for (int off = 1; off < 32; off <<= 1) {
        int n = __shfl_up_sync(0xFFFFFFFFu, incl, off);
        if (lane >= off) incl += n;
    }
    if (lane == 31) warp_sums[w] = incl;
    __syncthreads();

    if (w == 0) {
        int ws = warp_sums[lane];
        int wincl = ws;
#pragma unroll
        for (int off = 1; off < 32; off <<= 1) {
            int n = __shfl_up_sync(0xFFFFFFFFu, wincl, off);
            if (lane >= off) wincl += n;
        }
        warp_sums[lane] = wincl;
    }
    __syncthreads();

    int excl = incl - s + ((w > 0) ? warp_sums[w - 1] : 0);

    int run = excl;
#pragma unroll
    for (int i = 0; i < PER; i++) {
        if (base + i < N_NODES) {
            g_cursor[base + i] = run;
            g_count[base + i] = 0;      // restore for next graph replay
            run += c[i];
        }
    }
}

// ---------------------------------------------------------------------------
// Fill CSR payload: pos = atomicAdd(cursor[dst],1). After this kernel,
// g_cursor[n] == inclusive prefix == end offset of node n.
// ---------------------------------------------------------------------------
__global__ void __launch_bounds__(256) fill_kernel(
    const void* __restrict__ srcp, const void* __restrict__ dstp,
    const float* __restrict__ vals)
{
    __shared__ int s_flag;
    int t = threadIdx.x;
    int idx64 = block_sniff_idx64(srcp, t, &s_flag);

    int e0 = (blockIdx.x * 256 + t) * 4;
    if (e0 >= N_EDGES) return;

    int s[4], d[4];
    if (idx64) {
        const longlong2* ps = (const longlong2*)srcp;
        const longlong2* pd = (const longlong2*)dstp;
        longlong2 a = __ldg(&ps[e0 >> 1]);
        longlong2 b = __ldg(&ps[(e0 >> 1) + 1]);
        s[0] = (int)a.x; s[1] = (int)a.y; s[2] = (int)b.x; s[3] = (int)b.y;
        longlong2 cc = __ldg(&pd[e0 >> 1]);
        longlong2 dd = __ldg(&pd[(e0 >> 1) + 1]);
        d[0] = (int)cc.x; d[1] = (int)cc.y; d[2] = (int)dd.x; d[3] = (int)dd.y;
    } else {
        int4 a = __ldg(&((const int4*)srcp)[e0 >> 2]);
        s[0] = a.x; s[1] = a.y; s[2] = a.z; s[3] = a.w;
        int4 bb = __ldg(&((const int4*)dstp)[e0 >> 2]);
        d[0] = bb.x; d[1] = bb.y; d[2] = bb.z; d[3] = bb.w;
    }
    float4 v = __ldg(&((const float4*)vals)[e0 >> 2]);
    float vf[4] = {v.x, v.y, v.z, v.w};

#pragma unroll
    for (int i = 0; i < 4; i++) {
        int pos = atomicAdd(g_cursor + d[i], 1);
        g_esrc[pos] = s[i];
        g_eval[pos] = vf[i];
    }
}

// ---------------------------------------------------------------------------
// Aggregate: one warp per node. Coalesced (src,val) chunk loads + shuffle
// broadcast -> independent y-row gathers (deep MLP). Lane L owns cols [4L,4L+4).
// ---------------------------------------------------------------------------
__global__ void __launch_bounds__(256) aggregate_kernel(
    const float* __restrict__ b, float* __restrict__ out)
{
    int warp = (blockIdx.x * blockDim.x + threadIdx.x) >> 5;
    int lane = threadIdx.x & 31;
    if (warp >= N_NODES) return;
    int n = warp;

    int start = (n == 0) ? 0 : __ldg(g_cursor + n - 1);
    int end   = __ldg(g_cursor + n);

    const uint2* yv = (const uint2*)g_yh;  // 8B = 4 halves per lane

    float4 acc0 = make_float4(0.f, 0.f, 0.f, 0.f);
    float4 acc1 = make_float4(0.f, 0.f, 0.f, 0.f);

    for (int cbase = start; cbase < end; cbase += 32) {
        int idx = cbase + lane;
        int   sL = (idx < end) ? __ldg(g_esrc + idx) : 0;
        float vL = (idx < end) ? __ldg(g_eval + idx) : 0.f;
        int m = end - cbase; if (m > 32) m = 32;

        int j = 0;
        for (; j + 1 < m; j += 2) {
            int   s0 = __shfl_sync(0xFFFFFFFFu, sL, j);
            int   s1 = __shfl_sync(0xFFFFFFFFu, sL, j + 1);
            float v0 = __shfl_sync(0xFFFFFFFFu, vL, j);
            float v1 = __shfl_sync(0xFFFFFFFFu, vL, j + 1);

            uint2 r0 = __ldg(&yv[s0 * 32 + lane]);
            uint2 r1 = __ldg(&yv[s1 * 32 + lane]);

            float2 a0 = __half22float2(*(const __half2*)&r0.x);
            float2 b0 = __half22float2(*(const __half2*)&r0.y);
            acc0.x += v0 * a0.x; acc0.y += v0 * a0.y;
            acc0.z += v0 * b0.x; acc0.w += v0 * b0.y;

            float2 a1 = __half22float2(*(const __half2*)&r1.x);
            float2 b1 = __half22float2(*(const __half2*)&r1.y);
            acc1.x += v1 * a1.x; acc1.y += v1 * a1.y;
            acc1.z += v1 * b1.x; acc1.w += v1 * b1.y;
        }
        if (j < m) {
            int   s0 = __shfl_sync(0xFFFFFFFFu, sL, j);
            float v0 = __shfl_sync(0xFFFFFFFFu, vL, j);
            uint2 r0 = __ldg(&yv[s0 * 32 + lane]);
            float2 a0 = __half22float2(*(const __half2*)&r0.x);
            float2 b0 = __half22float2(*(const __half2*)&r0.y);
            acc0.x += v0 * a0.x; acc0.y += v0 * a0.y;
            acc0.z += v0 * b0.x; acc0.w += v0 * b0.y;
        }
    }

    float4 bias = __ldg(&((const float4*)b)[lane]);
    float4 r;
    r.x = acc0.x + acc1.x + bias.x;
    r.y = acc0.y + acc1.y + bias.y;
    r.z = acc0.z + acc1.z + bias.z;
    r.w = acc0.w + acc1.w + bias.w;
    ((float4*)out)[n * 32 + lane] = r;
}

// ---------------------------------------------------------------------------
// Launch: 4 graph nodes total.
// ---------------------------------------------------------------------------
extern "C" void kernel_launch(void* const* d_in, const int* in_sizes, int n_in,
                              void* d_out, int out_size)
{
    const float* x    = (const float*)d_in[0];
    const void*  srcp = d_in[1];
    const void*  dstp = d_in[2];
    const float* vals = (const float*)d_in[3];
    const float* W    = (const float*)d_in[4];
    const float* b    = (const float*)d_in[5];
    float* out = (float*)d_out;

    gemm_hist_kernel<<<GEMM_BLOCKS + HIST_BLOCKS, 256>>>(x, W, dstp);
    scan_kernel<<<1, 1024>>>();
    fill_kernel<<<(N_EDGES + 1023) / 1024, 256>>>(srcp, dstp, vals);
    aggregate_kernel<<<(N_NODES * 32 + 255) / 256, 256>>>(b, out);
}

// round 4
// speedup vs baseline: 1.0559x; 1.0559x over previous
#include <cuda_runtime.h>
#include <cuda_fp16.h>
#include <cstdint>

#define N_NODES 10000
#define N_EDGES 640000
#define D 128

#define GEMM_BLOCKS 1250   // 8 nodes per block
#define HIST_BLOCKS 625    // 1024 edges per block (exact: 625*1024 = 640000)

// ---- allocation-free scratch ----------------------------------------------
__device__ __half              g_yh[N_NODES * D]; // y = x@W^T, fp16 (2.5MB)
__device__ int                 g_count[N_NODES];  // zero-init; scan re-zeroes
__device__ int                 g_cursor[N_NODES]; // excl prefix -> incl after fill
__device__ unsigned long long  g_epack[N_EDGES];  // (val<<32)|src, permuted by dst

// Per-block index-dtype sniff: warp 0 tests 32 int64-interpretations.
// For int32 data, P(all valid node ids) ~ (1e-4)^32 -> effectively 0.
__device__ __forceinline__ int block_sniff_idx64(const void* idxp, int t,
                                                 int* s_flag) {
    if (t < 32) {
        long long v = ((const long long*)idxp)[t];
        int ok = (v >= 0 && v < N_NODES);
        int all = __all_sync(0xFFFFFFFFu, ok);
        if (t == 0) *s_flag = all;
    }
    __syncthreads();
    return *s_flag;
}

// ---------------------------------------------------------------------------
// Fused: blocks [0,GEMM_BLOCKS) -> y = x@W^T (fp16); rest -> dst histogram.
// ---------------------------------------------------------------------------
__global__ void __launch_bounds__(256) gemm_hist_kernel(
    const float* __restrict__ x, const float* __restrict__ W,
    const void* __restrict__ dstp)
{
    int t = threadIdx.x;

    if (blockIdx.x < GEMM_BLOCKS) {
        __shared__ float4 xs[8][32];
        int n0 = blockIdx.x * 8;
        int o  = t & 127;
        int g  = t >> 7;
        {
            int n = t >> 5, c = t & 31;
            int node = n0 + n;
            xs[n][c] = (node < N_NODES) ? ((const float4*)x)[node * 32 + c]
                                        : make_float4(0.f, 0.f, 0.f, 0.f);
        }
        __syncthreads();

        float acc[4] = {0.f, 0.f, 0.f, 0.f};
        const float4* Wo = (const float4*)(W + o * D);
#pragma unroll 8
        for (int c = 0; c < 32; c++) {
            float4 w = __ldg(&Wo[c]);
#pragma unroll
            for (int n = 0; n < 4; n++) {
                float4 xv = xs[g * 4 + n][c];
                acc[n] += w.x * xv.x + w.y * xv.y + w.z * xv.z + w.w * xv.w;
            }
        }
#pragma unroll
        for (int n = 0; n < 4; n++) {
            int node = n0 + g * 4 + n;
            if (node < N_NODES) g_yh[node * D + o] = __float2half(acc[n]);
        }
    } else {
        __shared__ int s_flag;
        int idx64 = block_sniff_idx64(dstp, t, &s_flag);

        int hb = blockIdx.x - GEMM_BLOCKS;
        int e0 = (hb * 256 + t) * 4;

        int d0, d1, d2, d3;
        if (idx64) {
            const longlong2* p = (const longlong2*)dstp;
            longlong2 a = __ldg(&p[e0 >> 1]);
            longlong2 c = __ldg(&p[(e0 >> 1) + 1]);
            d0 = (int)a.x; d1 = (int)a.y; d2 = (int)c.x; d3 = (int)c.y;
        } else {
            int4 a = __ldg(&((const int4*)dstp)[e0 >> 2]);
            d0 = a.x; d1 = a.y; d2 = a.z; d3 = a.w;
        }
        asm volatile("red.global.add.s32 [%0], %1;" :: "l"(g_count + d0), "r"(1) : "memory");
        asm volatile("red.global.add.s32 [%0], %1;" :: "l"(g_count + d1), "r"(1) : "memory");
        asm volatile("red.global.add.s32 [%0], %1;" :: "l"(g_count + d2), "r"(1) : "memory");
        asm volatile("red.global.add.s32 [%0], %1;" :: "l"(g_count + d3), "r"(1) : "memory");
    }
}

// ---------------------------------------------------------------------------
// Shuffle-based exclusive scan: 1024 threads x 10 nodes each. Also re-zeroes
// g_count for the next graph replay.
// ---------------------------------------------------------------------------
__global__ void __launch_bounds__(1024) scan_kernel() {
    __shared__ int warp_sums[32];
    const int PER = 10;
    int t = threadIdx.x;
    int lane = t & 31, w = t >> 5;
    int base = t * PER;

    int c[PER];
    int s = 0;
#pragma unroll
    for (int i = 0; i < PER; i++) {
        c[i] = (base + i < N_NODES) ? g_count[base + i] : 0;
        s += c[i];
    }

    int incl = s;
#pragma unroll
    for (int off = 1; off < 32; off <<= 1) {
        int nb = __shfl_up_sync(0xFFFFFFFFu, incl, off);
        if (lane >= off) incl += nb;
    }
    if (lane == 31) warp_sums[w] = incl;
    __syncthreads();

    if (w == 0) {
        int wincl = warp_sums[lane];
#pragma unroll
        for (int off = 1; off < 32; off <<= 1) {
            int nb = __shfl_up_sync(0xFFFFFFFFu, wincl, off);
            if (lane >= off) wincl += nb;
        }
        warp_sums[lane] = wincl;
    }
    __syncthreads();

    int run = incl - s + ((w > 0) ? warp_sums[w - 1] : 0);
#pragma unroll
    for (int i = 0; i < PER; i++) {
        if (base + i < N_NODES) {
            g_cursor[base + i] = run;
            g_count[base + i] = 0;
            run += c[i];
        }
    }
}

// ---------------------------------------------------------------------------
// Fill CSR payload: pos = atomicAdd(cursor[dst],1); one packed 8B store.
// After this kernel g_cursor[n] == inclusive prefix == end offset.
// ---------------------------------------------------------------------------
__global__ void __launch_bounds__(256) fill_kernel(
    const void* __restrict__ srcp, const void* __restrict__ dstp,
    const float* __restrict__ vals)
{
    __shared__ int s_flag;
    int t = threadIdx.x;
    int idx64 = block_sniff_idx64(srcp, t, &s_flag);

    int e0 = (blockIdx.x * 256 + t) * 4;
    if (e0 >= N_EDGES) return;

    int s[4], d[4];
    if (idx64) {
        const longlong2* ps = (const longlong2*)srcp;
        const longlong2* pd = (const longlong2*)dstp;
        longlong2 a = __ldg(&ps[e0 >> 1]);
        longlong2 b2 = __ldg(&ps[(e0 >> 1) + 1]);
        s[0] = (int)a.x; s[1] = (int)a.y; s[2] = (int)b2.x; s[3] = (int)b2.y;
        longlong2 cc = __ldg(&pd[e0 >> 1]);
        longlong2 dd = __ldg(&pd[(e0 >> 1) + 1]);
        d[0] = (int)cc.x; d[1] = (int)cc.y; d[2] = (int)dd.x; d[3] = (int)dd.y;
    } else {
        int4 a = __ldg(&((const int4*)srcp)[e0 >> 2]);
        s[0] = a.x; s[1] = a.y; s[2] = a.z; s[3] = a.w;
        int4 bb = __ldg(&((const int4*)dstp)[e0 >> 2]);
        d[0] = bb.x; d[1] = bb.y; d[2] = bb.z; d[3] = bb.w;
    }
    float4 v = __ldg(&((const float4*)vals)[e0 >> 2]);
    float vf[4] = {v.x, v.y, v.z, v.w};

#pragma unroll
    for (int i = 0; i < 4; i++) {
        int pos = atomicAdd(g_cursor + d[i], 1);
        unsigned long long pk =
            (unsigned long long)(unsigned)s[i] |
            ((unsigned long long)__float_as_uint(vf[i]) << 32);
        g_epack[pos] = pk;
    }
}

// ---------------------------------------------------------------------------
// Aggregate: one warp per node, 2 edges per iteration.
// Lanes 0-15 process the even edge, lanes 16-31 the odd edge; each lane owns
// 8 columns (one LDG.128 of fp16 y-row). fp32 accumulation; xor-16 combine
// at the end; lanes 0-15 write 2x float4 + bias. No shuffles in the loop.
// ---------------------------------------------------------------------------
__device__ __forceinline__ void accum8(float* acc, uint4 r, float v) {
    float2 f;
    f = __half22float2(*(const __half2*)&r.x); acc[0] += v * f.x; acc[1] += v * f.y;
    f = __half22float2(*(const __half2*)&r.y); acc[2] += v * f.x; acc[3] += v * f.y;
    f = __half22float2(*(const __half2*)&r.z); acc[4] += v * f.x; acc[5] += v * f.y;
    f = __half22float2(*(const __half2*)&r.w); acc[6] += v * f.x; acc[7] += v * f.y;
}

__global__ void __launch_bounds__(256) aggregate_kernel(
    const float* __restrict__ b, float* __restrict__ out)
{
    int warp = (blockIdx.x * blockDim.x + threadIdx.x) >> 5;
    int lane = threadIdx.x & 31;
    if (warp >= N_NODES) return;
    int n = warp;

    int start = (n == 0) ? 0 : __ldg(g_cursor + n - 1);
    int end   = __ldg(g_cursor + n);

    int half = lane >> 4;   // 0: even edge of pair, 1: odd edge
    int c    = lane & 15;   // column block: cols [8c, 8c+8)

    const uint4* yv = (const uint4*)g_yh;  // row stride = 16 uint4

    float acc0[8] = {0,0,0,0,0,0,0,0};
    float acc1[8] = {0,0,0,0,0,0,0,0};

    int base = start;
    // main: 4 edges per iteration
    for (; base + 4 <= end; base += 4) {
        unsigned long long e0 = __ldg(g_epack + base + half);
        unsigned long long e1 = __ldg(g_epack + base + 2 + half);
        int   s0 = (int)(unsigned)e0;
        float v0 = __uint_as_float((unsigned)(e0 >> 32));
        int   s1 = (int)(unsigned)e1;
        float v1 = __uint_as_float((unsigned)(e1 >> 32));
        uint4 r0 = __ldg(&yv[s0 * 16 + c]);
        uint4 r1 = __ldg(&yv[s1 * 16 + c]);
        accum8(acc0, r0, v0);
        accum8(acc1, r1, v1);
    }
    // tail: 2 edges per iteration, predicated
    for (; base < end; base += 2) {
        int i = base + half;
        bool act = (i < end);
        int ii = act ? i : base;
        unsigned long long e0 = __ldg(g_epack + ii);
        int   s0 = (int)(unsigned)e0;
        float v0 = act ? __uint_as_float((unsigned)(e0 >> 32)) : 0.f;
        uint4 r0 = __ldg(&yv[s0 * 16 + c]);
        accum8(acc0, r0, v0);
    }

#pragma unroll
    for (int k = 0; k < 8; k++) acc0[k] += acc1[k];
#pragma unroll
    for (int k = 0; k < 8; k++)
        acc0[k] += __shfl_xor_sync(0xFFFFFFFFu, acc0[k], 16);

    if (lane < 16) {
        float4 b0 = __ldg(&((const float4*)b)[c * 2]);
        float4 b1 = __ldg(&((const float4*)b)[c * 2 + 1]);
        float4 w0 = make_float4(acc0[0] + b0.x, acc0[1] + b0.y,
                                acc0[2] + b0.z, acc0[3] + b0.w);
        float4 w1 = make_float4(acc0[4] + b1.x, acc0[5] + b1.y,
                                acc0[6] + b1.z, acc0[7] + b1.w);
        ((float4*)out)[n * 32 + c * 2]     = w0;
        ((float4*)out)[n * 32 + c * 2 + 1] = w1;
    }
}

// ---------------------------------------------------------------------------
// Launch: 4 graph nodes.
// ---------------------------------------------------------------------------
extern "C" void kernel_launch(void* const* d_in, const int* in_sizes, int n_in,
                              void* d_out, int out_size)
{
    const float* x    = (const float*)d_in[0];
    const void*  srcp = d_in[1];
    const void*  dstp = d_in[2];
    const float* vals = (const float*)d_in[3];
    const float* W    = (const float*)d_in[4];
    const float* b    = (const float*)d_in[5];
    float* out = (float*)d_out;

    gemm_hist_kernel<<<GEMM_BLOCKS + HIST_BLOCKS, 256>>>(x, W, dstp);
    scan_kernel<<<1, 1024>>>();
    fill_kernel<<<(N_EDGES + 1023) / 1024, 256>>>(srcp, dstp, vals);
    aggregate_kernel<<<(N_NODES * 32 + 255) / 256, 256>>>(b, out);
}